// round 15
// baseline (speedup 1.0000x reference)
#include <cuda_runtime.h>
#include <cuda_bf16.h>
#include <cstdint>

#define M_TOTAL 8192
#define KDIM    128
#define INVT    5.0f

// ---- device globals (no allocation allowed) -------------------------------
__device__ __align__(16) uint8_t f8G[M_TOTAL * KDIM];   // e4m3 features
__device__ float    dG[M_TOTAL];
__device__ float    accG[M_TOTAL];
__device__ unsigned mG[M_TOTAL];
__device__ int      labG[M_TOTAL];
__device__ unsigned dminEnc = 0xFFFFFFFFu;   // encoded global min of dG

// ---- helpers --------------------------------------------------------------
__device__ __forceinline__ uint32_t smem_to_u32(const void* p) {
    uint32_t a;
    asm("{ .reg .u64 t; cvta.to.shared.u64 t, %1; cvt.u32.u64 %0, t; }" : "=r"(a) : "l"(p));
    return a;
}
__device__ __forceinline__ void cpa16(uint32_t dst, const void* src) {
    asm volatile("cp.async.cg.shared.global [%0], [%1], 16;" :: "r"(dst), "l"(src) : "memory");
}
__device__ __forceinline__ void ldsm4(uint32_t* r, uint32_t addr) {
    asm volatile("ldmatrix.sync.aligned.m8n8.x4.shared.b16 {%0,%1,%2,%3}, [%4];"
                 : "=r"(r[0]), "=r"(r[1]), "=r"(r[2]), "=r"(r[3]) : "r"(addr));
}
// fp8 e4m3 MMA: D(16x8,f32) += A(16x32,e4m3) * B(32x8,e4m3)
__device__ __forceinline__ void mma16832f8(float* c, const uint32_t* a, uint32_t b0, uint32_t b1) {
    asm volatile("mma.sync.aligned.m16n8k32.row.col.f32.e4m3.e4m3.f32 "
                 "{%0,%1,%2,%3}, {%4,%5,%6,%7}, {%8,%9}, {%0,%1,%2,%3};"
                 : "+f"(c[0]), "+f"(c[1]), "+f"(c[2]), "+f"(c[3])
                 : "r"(a[0]), "r"(a[1]), "r"(a[2]), "r"(a[3]), "r"(b0), "r"(b1));
}
// pack 2 floats -> e4m3x2 (x0 -> low byte, x1 -> high byte)
__device__ __forceinline__ uint16_t pk_e4m3x2(float x0, float x1) {
    uint16_t r;
    asm("cvt.rn.satfinite.e4m3x2.f32 %0, %1, %2;" : "=h"(r) : "f"(x1), "f"(x0));
    return r;
}
// order-preserving float <-> unsigned (atomicMax/atomicMin on floats)
__device__ __forceinline__ unsigned fenc(float f) {
    unsigned u = __float_as_uint(f);
    return (u >> 31) ? ~u : (u | 0x80000000u);
}
__device__ __forceinline__ float fdec(unsigned e) {
    return (e >> 31) ? __uint_as_float(e & 0x7fffffffu) : __uint_as_float(~e);
}

// ---- kernel 1: e4m3 cast, per-row norms (exact fp32), init ---------------
__global__ void __launch_bounds__(256)
prep_kernel(const float* __restrict__ feat, const long long* __restrict__ labels) {
    const int g   = blockIdx.x * 256 + threadIdx.x;
    const int row = g >> 4;
    const int sub = g & 15;               // 8 floats per thread
    const float4* src = reinterpret_cast<const float4*>(feat + (size_t)row * KDIM + sub * 8);
    float4 v0 = src[0], v1 = src[1];

    float ss = v0.x*v0.x + v0.y*v0.y + v0.z*v0.z + v0.w*v0.w
             + v1.x*v1.x + v1.y*v1.y + v1.z*v1.z + v1.w*v1.w;

    uint32_t w0 = (uint32_t)pk_e4m3x2(v0.x, v0.y) | ((uint32_t)pk_e4m3x2(v0.z, v0.w) << 16);
    uint32_t w1 = (uint32_t)pk_e4m3x2(v1.x, v1.y) | ((uint32_t)pk_e4m3x2(v1.z, v1.w) << 16);
    *reinterpret_cast<uint2*>(f8G + (size_t)row * KDIM + sub * 8) = make_uint2(w0, w1);

    #pragma unroll
    for (int o = 8; o; o >>= 1) ss += __shfl_xor_sync(0xffffffffu, ss, o);
    if (sub == 0) {
        float d = ss * INVT;
        dG[row]   = d;
        accG[row] = 0.0f;
        mG[row]   = 0u;
        labG[row] = (int)labels[row];
        atomicMin(&dminEnc, fenc(d));
    }
}

// ---- kernel 2: symmetric FP8 MMA GEMM, deferred-check dual-sided epilogue
// Tiles tj >= ti only. 128x128 tile (16KB/tile fp8), 8 warps (4x2), 32x64.

#define SMEM_A   0
#define SMEM_B   16384
#define SMEM_SZ  32768

__global__ void __launch_bounds__(256, 2)
main_kernel() {
    const int ti = blockIdx.y, tj = blockIdx.x;
    if (tj < ti) return;
    const bool diag = (ti == tj);

    extern __shared__ char smem[];
    const uint32_t sb = smem_to_u32(smem);
    const int t = threadIdx.x;
    const int lane = t & 31, wid = t >> 5;
    const int wm = wid & 3, wn = wid >> 2;
    const int rowbase = ti * 128;
    const int colbase = tj * 128;

    // ---- load A (rows) and B (cols) tiles, swizzled for ldmatrix ----
    // fp8 row = 128 B = 8 quads of 16 B; swizzle (q ^ (row&7))*16
    {
        const int q = t & 7, r0 = t >> 3;            // 32 base rows
        const uint32_t sw = (uint32_t)((q ^ (r0 & 7)) * 16);
        const uint8_t* Ag = f8G + (size_t)(rowbase + r0) * KDIM + q * 16;
        const uint8_t* Bg = f8G + (size_t)(colbase + r0) * KDIM + q * 16;
        #pragma unroll
        for (int j = 0; j < 4; j++) {
            cpa16(sb + SMEM_A + (r0 + j * 32) * 128 + sw, Ag + (size_t)j * 32 * KDIM);
            cpa16(sb + SMEM_B + (r0 + j * 32) * 128 + sw, Bg + (size_t)j * 32 * KDIM);
        }
    }
    asm volatile("cp.async.commit_group;" ::: "memory");
    asm volatile("cp.async.wait_group 0;" ::: "memory");
    __syncthreads();

    // ---- GEMM: K=128 in 4 steps of k32 ----
    float acc[2][8][4];
    #pragma unroll
    for (int mi = 0; mi < 2; mi++)
        #pragma unroll
        for (int bi = 0; bi < 8; bi++)
            #pragma unroll
            for (int rg = 0; rg < 4; rg++) acc[mi][bi][rg] = 0.f;

    #pragma unroll
    for (int ks = 0; ks < 4; ks++) {
        const int ql = ks * 2 + (lane >> 4);         // quad 0..7
        uint32_t af[2][4];
        #pragma unroll
        for (int mi = 0; mi < 2; mi++) {
            int row = wm * 32 + mi * 16 + (lane & 15);
            ldsm4(af[mi], sb + SMEM_A + row * 128 + ((ql ^ (row & 7)) * 16));
        }
        uint32_t bfm[4][4];
        #pragma unroll
        for (int bi = 0; bi < 4; bi++) {
            int row = wn * 64 + bi * 16 + (lane & 15);
            ldsm4(bfm[bi], sb + SMEM_B + row * 128 + ((ql ^ (row & 7)) * 16));
        }
        #pragma unroll
        for (int mi = 0; mi < 2; mi++)
            #pragma unroll
            for (int bi = 0; bi < 4; bi++) {
                mma16832f8(acc[mi][bi * 2 + 0], af[mi], bfm[bi][0], bfm[bi][2]);
                mma16832f8(acc[mi][bi * 2 + 1], af[mi], bfm[bi][1], bfm[bi][3]);
            }
    }

    // ---- row side: per-element FMAX only; exact deferred slow path ----
    #pragma unroll
    for (int s = 0; s < 4; s++) {
        const int gr = rowbase + wm * 32 + (s >> 1) * 16 + (s & 1) * 8 + (lane >> 2);
        float m = -1e30f;
        #pragma unroll
        for (int bi = 0; bi < 8; bi++) {
            m = fmaxf(m, acc[s >> 1][bi][(s & 1) * 2]);
            m = fmaxf(m, acc[s >> 1][bi][(s & 1) * 2 + 1]);
        }
        m = fmaxf(m, __shfl_xor_sync(0xffffffffu, m, 1));
        m = fmaxf(m, __shfl_xor_sync(0xffffffffu, m, 2));     // row max (raw s), all lanes
        const float d = dG[gr];
        if (__builtin_expect(m * INVT - d > -75.f, 0)) {
            // exact slow path: rescan this lane's 16 elements of row gr
            const int lr = labG[gr];
            #pragma unroll
            for (int bi = 0; bi < 8; bi++)
                #pragma unroll
                for (int rgl = 0; rgl < 2; rgl++) {
                    float sim = acc[s >> 1][bi][(s & 1) * 2 + rgl] * INVT;
                    float tt  = sim - d;
                    if (tt > -75.f) {
                        int c = colbase + wn * 64 + bi * 8 + (lane & 3) * 2 + rgl;
                        if (c != gr) {
                            float e = __expf(tt);
                            atomicAdd(&accG[gr], (lr == labG[c]) ? e : -e);
                        }
                    }
                }
        }
        if ((lane & 3) == 0) atomicMax(&mG[gr], fenc(m * INVT));
    }

    // ---- col side (transposed contribution), off-diagonal tiles only ----
    if (!diag) {
        const float thrC = fdec(dminEnc) * 0.2f - 15.f;   // conservative raw-s threshold
        #pragma unroll
        for (int bi = 0; bi < 8; bi++)
            #pragma unroll
            for (int rgl = 0; rgl < 2; rgl++) {
                float m = fmaxf(fmaxf(acc[0][bi][rgl], acc[0][bi][2 + rgl]),
                                fmaxf(acc[1][bi][rgl], acc[1][bi][2 + rgl]));
                m = fmaxf(m, __shfl_xor_sync(0xffffffffu, m, 4));
                m = fmaxf(m, __shfl_xor_sync(0xffffffffu, m, 8));
                m = fmaxf(m, __shfl_xor_sync(0xffffffffu, m, 16));  // col max, all lanes
                if (__builtin_expect(m > thrC, 0)) {
                    // exact slow path for this lane's column
                    const int c  = colbase + wn * 64 + bi * 8 + (lane & 3) * 2 + rgl;
                    const float dc = dG[c];
                    const int lc = labG[c];
                    #pragma unroll
                    for (int mi = 0; mi < 2; mi++)
                        #pragma unroll
                        for (int rgh = 0; rgh < 2; rgh++) {
                            float sim = acc[mi][bi][rgh * 2 + rgl] * INVT;
                            float tt  = sim - dc;
                            if (tt > -75.f) {
                                int r = rowbase + wm * 32 + mi * 16 + rgh * 8 + (lane >> 2);
                                float e = __expf(tt);
                                atomicAdd(&accG[c], (labG[r] == lc) ? e : -e);
                            }
                        }
                }
                if (lane < 4) {
                    int c = colbase + wn * 64 + bi * 8 + lane * 2 + rgl;
                    atomicMax(&mG[c], fenc(m * INVT));
                }
            }
    }
}

// ---- kernel 3: exact max rebase + mean -----------------------------------
__global__ void final_kernel(float* __restrict__ out) {
    __shared__ double red[32];
    const int t = threadIdx.x, lane = t & 31, warp = t >> 5;
    double s = 0.0;
    #pragma unroll
    for (int i = 0; i < 8; i++) {
        int r = t + i * 1024;
        float m = fdec(mG[r]);
        s += (double)(accG[r] * __expf(dG[r] - m));
    }
    #pragma unroll
    for (int o = 16; o; o >>= 1) s += __shfl_xor_sync(0xffffffffu, s, o);
    if (lane == 0) red[warp] = s;
    __syncthreads();
    if (warp == 0) {
        double v = red[lane];
        #pragma unroll
        for (int o = 16; o; o >>= 1) v += __shfl_xor_sync(0xffffffffu, v, o);
        if (lane == 0) out[0] = (float)(-v / (double)M_TOTAL);
    }
}

// ---- host ----------------------------------------------------------------
extern "C" void kernel_launch(void* const* d_in, const int* in_sizes, int n_in,
                              void* d_out, int out_size) {
    const float*     feat   = (const float*)d_in[0];
    const long long* labels = (const long long*)d_in[1];
    float* out = (float*)d_out;

    cudaFuncSetAttribute(main_kernel, cudaFuncAttributeMaxDynamicSharedMemorySize, SMEM_SZ);

    prep_kernel<<<M_TOTAL * 16 / 256, 256>>>(feat, labels);
    main_kernel<<<dim3(64, 64), 256, SMEM_SZ>>>();
    final_kernel<<<1, 1024>>>(out);
}

// round 16
// speedup vs baseline: 1.3352x; 1.3352x over previous
#include <cuda_runtime.h>
#include <cuda_bf16.h>
#include <cstdint>

#define M_TOTAL 8192
#define KDIM    128
#define INVT    5.0f

// ---- device globals (no allocation allowed) -------------------------------
__device__ __align__(16) uint8_t f8G[M_TOTAL * KDIM];   // e4m3 features
__device__ float    dG[M_TOTAL];
__device__ float    accG[M_TOTAL];
__device__ unsigned mG[M_TOTAL];
__device__ int      labG[M_TOTAL];
__device__ unsigned dminEnc = 0xFFFFFFFFu;   // encoded global min of dG

// ---- helpers --------------------------------------------------------------
__device__ __forceinline__ uint32_t smem_to_u32(const void* p) {
    uint32_t a;
    asm("{ .reg .u64 t; cvta.to.shared.u64 t, %1; cvt.u32.u64 %0, t; }" : "=r"(a) : "l"(p));
    return a;
}
__device__ __forceinline__ void cpa16(uint32_t dst, const void* src) {
    asm volatile("cp.async.cg.shared.global [%0], [%1], 16;" :: "r"(dst), "l"(src) : "memory");
}
__device__ __forceinline__ void ldsm4(uint32_t* r, uint32_t addr) {
    asm volatile("ldmatrix.sync.aligned.m8n8.x4.shared.b16 {%0,%1,%2,%3}, [%4];"
                 : "=r"(r[0]), "=r"(r[1]), "=r"(r[2]), "=r"(r[3]) : "r"(addr));
}
// fp8 e4m3 MMA: D(16x8,f32) += A(16x32,e4m3) * B(32x8,e4m3)
__device__ __forceinline__ void mma16832f8(float* c, const uint32_t* a, uint32_t b0, uint32_t b1) {
    asm volatile("mma.sync.aligned.m16n8k32.row.col.f32.e4m3.e4m3.f32 "
                 "{%0,%1,%2,%3}, {%4,%5,%6,%7}, {%8,%9}, {%0,%1,%2,%3};"
                 : "+f"(c[0]), "+f"(c[1]), "+f"(c[2]), "+f"(c[3])
                 : "r"(a[0]), "r"(a[1]), "r"(a[2]), "r"(a[3]), "r"(b0), "r"(b1));
}
// pack 2 floats -> e4m3x2 (x0 -> low byte, x1 -> high byte)
__device__ __forceinline__ uint16_t pk_e4m3x2(float x0, float x1) {
    uint16_t r;
    asm("cvt.rn.satfinite.e4m3x2.f32 %0, %1, %2;" : "=h"(r) : "f"(x1), "f"(x0));
    return r;
}
// order-preserving float <-> unsigned (atomicMax/atomicMin on floats)
__device__ __forceinline__ unsigned fenc(float f) {
    unsigned u = __float_as_uint(f);
    return (u >> 31) ? ~u : (u | 0x80000000u);
}
__device__ __forceinline__ float fdec(unsigned e) {
    return (e >> 31) ? __uint_as_float(e & 0x7fffffffu) : __uint_as_float(~e);
}

// ---- kernel 1: e4m3 cast, per-row norms (exact fp32), init ---------------
__global__ void __launch_bounds__(256)
prep_kernel(const float* __restrict__ feat, const long long* __restrict__ labels) {
    const int g   = blockIdx.x * 256 + threadIdx.x;
    const int row = g >> 4;
    const int sub = g & 15;               // 8 floats per thread
    const float4* src = reinterpret_cast<const float4*>(feat + (size_t)row * KDIM + sub * 8);
    float4 v0 = src[0], v1 = src[1];

    float ss = v0.x*v0.x + v0.y*v0.y + v0.z*v0.z + v0.w*v0.w
             + v1.x*v1.x + v1.y*v1.y + v1.z*v1.z + v1.w*v1.w;

    uint32_t w0 = (uint32_t)pk_e4m3x2(v0.x, v0.y) | ((uint32_t)pk_e4m3x2(v0.z, v0.w) << 16);
    uint32_t w1 = (uint32_t)pk_e4m3x2(v1.x, v1.y) | ((uint32_t)pk_e4m3x2(v1.z, v1.w) << 16);
    *reinterpret_cast<uint2*>(f8G + (size_t)row * KDIM + sub * 8) = make_uint2(w0, w1);

    #pragma unroll
    for (int o = 8; o; o >>= 1) ss += __shfl_xor_sync(0xffffffffu, ss, o);
    if (sub == 0) {
        float d = ss * INVT;
        dG[row]   = d;
        accG[row] = 0.0f;
        mG[row]   = fenc(d);      // safe finite init: exact when accG stays 0
        labG[row] = (int)labels[row];
        atomicMin(&dminEnc, fenc(d));
    }
}

// ---- kernel 2: symmetric FP8 MMA GEMM, hotness-gated epilogue ------------
// Tiles tj >= ti only. 128x128 tile (16KB/tile fp8), 8 warps (4x2), 32x64.

#define SMEM_A   0
#define SMEM_B   16384
#define SMEM_SZ  32768

__global__ void __launch_bounds__(256, 2)
main_kernel() {
    const int ti = blockIdx.y, tj = blockIdx.x;
    if (tj < ti) return;
    const bool diag = (ti == tj);

    extern __shared__ char smem[];
    const uint32_t sb = smem_to_u32(smem);
    const int t = threadIdx.x;
    const int lane = t & 31, wid = t >> 5;
    const int wm = wid & 3, wn = wid >> 2;
    const int rowbase = ti * 128;
    const int colbase = tj * 128;

    // ---- load A (rows) and B (cols) tiles, swizzled for ldmatrix ----
    {
        const int q = t & 7, r0 = t >> 3;            // 32 base rows
        const uint32_t sw = (uint32_t)((q ^ (r0 & 7)) * 16);
        const uint8_t* Ag = f8G + (size_t)(rowbase + r0) * KDIM + q * 16;
        const uint8_t* Bg = f8G + (size_t)(colbase + r0) * KDIM + q * 16;
        #pragma unroll
        for (int j = 0; j < 4; j++) {
            cpa16(sb + SMEM_A + (r0 + j * 32) * 128 + sw, Ag + (size_t)j * 32 * KDIM);
            cpa16(sb + SMEM_B + (r0 + j * 32) * 128 + sw, Bg + (size_t)j * 32 * KDIM);
        }
    }
    asm volatile("cp.async.commit_group;" ::: "memory");
    asm volatile("cp.async.wait_group 0;" ::: "memory");
    __syncthreads();

    // ---- GEMM: K=128 in 4 steps of k32 ----
    float acc[2][8][4];
    #pragma unroll
    for (int mi = 0; mi < 2; mi++)
        #pragma unroll
        for (int bi = 0; bi < 8; bi++)
            #pragma unroll
            for (int rg = 0; rg < 4; rg++) acc[mi][bi][rg] = 0.f;

    #pragma unroll
    for (int ks = 0; ks < 4; ks++) {
        const int ql = ks * 2 + (lane >> 4);         // quad 0..7
        uint32_t af[2][4];
        #pragma unroll
        for (int mi = 0; mi < 2; mi++) {
            int row = wm * 32 + mi * 16 + (lane & 15);
            ldsm4(af[mi], sb + SMEM_A + row * 128 + ((ql ^ (row & 7)) * 16));
        }
        uint32_t bfm[4][4];
        #pragma unroll
        for (int bi = 0; bi < 4; bi++) {
            int row = wn * 64 + bi * 16 + (lane & 15);
            ldsm4(bfm[bi], sb + SMEM_B + row * 128 + ((ql ^ (row & 7)) * 16));
        }
        #pragma unroll
        for (int mi = 0; mi < 2; mi++)
            #pragma unroll
            for (int bi = 0; bi < 4; bi++) {
                mma16832f8(acc[mi][bi * 2 + 0], af[mi], bfm[bi][0], bfm[bi][2]);
                mma16832f8(acc[mi][bi * 2 + 1], af[mi], bfm[bi][1], bfm[bi][3]);
            }
    }

    // ---- hotness detection: per-slot maxes (element-floor cost) ----
    const float thrC = fdec(dminEnc) * 0.2f - 15.f;   // raw-sim conservative threshold
    float m4[4];
    #pragma unroll
    for (int s = 0; s < 4; s++) {
        float m = -1e30f;
        #pragma unroll
        for (int bi = 0; bi < 8; bi++) {
            m = fmaxf(m, acc[s >> 1][bi][(s & 1) * 2]);
            m = fmaxf(m, acc[s >> 1][bi][(s & 1) * 2 + 1]);
        }
        m4[s] = m;
    }
    const float tmax = fmaxf(fmaxf(m4[0], m4[1]), fmaxf(m4[2], m4[3]));
    const bool hot = __any_sync(0xffffffffu, tmax > thrC);

    if (__builtin_expect(hot, 0)) {
        // ---- full exact epilogue (rare: diagonal tiles + any true outlier) ----
        // row side
        #pragma unroll
        for (int s = 0; s < 4; s++) {
            const int gr = rowbase + wm * 32 + (s >> 1) * 16 + (s & 1) * 8 + (lane >> 2);
            float m = m4[s];
            m = fmaxf(m, __shfl_xor_sync(0xffffffffu, m, 1));
            m = fmaxf(m, __shfl_xor_sync(0xffffffffu, m, 2));
            const float d = dG[gr];
            if (m * INVT - d > -75.f) {
                const int lr = labG[gr];
                #pragma unroll
                for (int bi = 0; bi < 8; bi++)
                    #pragma unroll
                    for (int rgl = 0; rgl < 2; rgl++) {
                        float sim = acc[s >> 1][bi][(s & 1) * 2 + rgl] * INVT;
                        float tt  = sim - d;
                        if (tt > -75.f) {
                            int c = colbase + wn * 64 + bi * 8 + (lane & 3) * 2 + rgl;
                            if (c != gr) {
                                float e = __expf(tt);
                                atomicAdd(&accG[gr], (lr == labG[c]) ? e : -e);
                            }
                        }
                    }
            }
            if ((lane & 3) == 0) atomicMax(&mG[gr], fenc(m * INVT));
        }
        // col side (transposed contribution), off-diagonal tiles only
        if (!diag) {
            #pragma unroll
            for (int bi = 0; bi < 8; bi++)
                #pragma unroll
                for (int rgl = 0; rgl < 2; rgl++) {
                    float m = fmaxf(fmaxf(acc[0][bi][rgl], acc[0][bi][2 + rgl]),
                                    fmaxf(acc[1][bi][rgl], acc[1][bi][2 + rgl]));
                    m = fmaxf(m, __shfl_xor_sync(0xffffffffu, m, 4));
                    m = fmaxf(m, __shfl_xor_sync(0xffffffffu, m, 8));
                    m = fmaxf(m, __shfl_xor_sync(0xffffffffu, m, 16));
                    if (m > thrC) {
                        const int c  = colbase + wn * 64 + bi * 8 + (lane & 3) * 2 + rgl;
                        const float dc = dG[c];
                        const int lc = labG[c];
                        #pragma unroll
                        for (int mi = 0; mi < 2; mi++)
                            #pragma unroll
                            for (int rgh = 0; rgh < 2; rgh++) {
                                float sim = acc[mi][bi][rgh * 2 + rgl] * INVT;
                                float tt  = sim - dc;
                                if (tt > -75.f) {
                                    int r = rowbase + wm * 32 + mi * 16 + rgh * 8 + (lane >> 2);
                                    float e = __expf(tt);
                                    atomicAdd(&accG[c], (labG[r] == lc) ? e : -e);
                                }
                            }
                    }
                    if (lane < 4) {
                        int c = colbase + wn * 64 + bi * 8 + lane * 2 + rgl;
                        atomicMax(&mG[c], fenc(m * INVT));
                    }
                }
        }
    }
    // non-hot warps: contribute nothing (proof: any element passing a per-element
    // exp guard implies raw > thrC -> warp hot; if accG[r] != 0, the warp owning
    // the true row max is hot and writes it; if accG[r] == 0, mG init dG suffices).
}

// ---- kernel 3: exact max rebase + mean -----------------------------------
__global__ void final_kernel(float* __restrict__ out) {
    __shared__ double red[32];
    const int t = threadIdx.x, lane = t & 31, warp = t >> 5;
    double s = 0.0;
    #pragma unroll
    for (int i = 0; i < 8; i++) {
        int r = t + i * 1024;
        float m = fdec(mG[r]);
        s += (double)(accG[r] * __expf(dG[r] - m));
    }
    #pragma unroll
    for (int o = 16; o; o >>= 1) s += __shfl_xor_sync(0xffffffffu, s, o);
    if (lane == 0) red[warp] = s;
    __syncthreads();
    if (warp == 0) {
        double v = red[lane];
        #pragma unroll
        for (int o = 16; o; o >>= 1) v += __shfl_xor_sync(0xffffffffu, v, o);
        if (lane == 0) out[0] = (float)(-v / (double)M_TOTAL);
    }
}

// ---- host ----------------------------------------------------------------
extern "C" void kernel_launch(void* const* d_in, const int* in_sizes, int n_in,
                              void* d_out, int out_size) {
    const float*     feat   = (const float*)d_in[0];
    const long long* labels = (const long long*)d_in[1];
    float* out = (float*)d_out;

    cudaFuncSetAttribute(main_kernel, cudaFuncAttributeMaxDynamicSharedMemorySize, SMEM_SZ);

    prep_kernel<<<M_TOTAL * 16 / 256, 256>>>(feat, labels);
    main_kernel<<<dim3(64, 64), 256, SMEM_SZ>>>();
    final_kernel<<<1, 1024>>>(out);
}

// round 17
// speedup vs baseline: 1.4753x; 1.1049x over previous
#include <cuda_runtime.h>
#include <cuda_bf16.h>
#include <cstdint>

#define M_TOTAL 8192
#define KDIM    128
#define INVT    5.0f

// ---- device globals (no allocation allowed) -------------------------------
__device__ __align__(16) uint8_t f8G[M_TOTAL * KDIM];   // e4m3 features
__device__ float    dG[M_TOTAL];
__device__ float    accG[M_TOTAL];
__device__ unsigned mG[M_TOTAL];
__device__ int      labG[M_TOTAL];
__device__ unsigned dminEnc = 0xFFFFFFFFu;   // encoded global min of dG

// ---- helpers --------------------------------------------------------------
__device__ __forceinline__ uint32_t smem_to_u32(const void* p) {
    uint32_t a;
    asm("{ .reg .u64 t; cvta.to.shared.u64 t, %1; cvt.u32.u64 %0, t; }" : "=r"(a) : "l"(p));
    return a;
}
__device__ __forceinline__ void cpa16(uint32_t dst, const void* src) {
    asm volatile("cp.async.cg.shared.global [%0], [%1], 16;" :: "r"(dst), "l"(src) : "memory");
}
__device__ __forceinline__ void ldsm4(uint32_t* r, uint32_t addr) {
    asm volatile("ldmatrix.sync.aligned.m8n8.x4.shared.b16 {%0,%1,%2,%3}, [%4];"
                 : "=r"(r[0]), "=r"(r[1]), "=r"(r[2]), "=r"(r[3]) : "r"(addr));
}
// fp8 e4m3 MMA: D(16x8,f32) += A(16x32,e4m3) * B(32x8,e4m3)
__device__ __forceinline__ void mma16832f8(float* c, const uint32_t* a, uint32_t b0, uint32_t b1) {
    asm volatile("mma.sync.aligned.m16n8k32.row.col.f32.e4m3.e4m3.f32 "
                 "{%0,%1,%2,%3}, {%4,%5,%6,%7}, {%8,%9}, {%0,%1,%2,%3};"
                 : "+f"(c[0]), "+f"(c[1]), "+f"(c[2]), "+f"(c[3])
                 : "r"(a[0]), "r"(a[1]), "r"(a[2]), "r"(a[3]), "r"(b0), "r"(b1));
}
// pack 2 floats -> e4m3x2 (x0 -> low byte, x1 -> high byte)
__device__ __forceinline__ uint16_t pk_e4m3x2(float x0, float x1) {
    uint16_t r;
    asm("cvt.rn.satfinite.e4m3x2.f32 %0, %1, %2;" : "=h"(r) : "f"(x1), "f"(x0));
    return r;
}
// order-preserving float <-> unsigned (atomicMax/atomicMin on floats)
__device__ __forceinline__ unsigned fenc(float f) {
    unsigned u = __float_as_uint(f);
    return (u >> 31) ? ~u : (u | 0x80000000u);
}
__device__ __forceinline__ float fdec(unsigned e) {
    return (e >> 31) ? __uint_as_float(e & 0x7fffffffu) : __uint_as_float(~e);
}

// ---- kernel 1: e4m3 cast, per-row norms (exact fp32), init ---------------
// Single delta vs R16: dminEnc atomic pre-reduced per block (8192 -> 512 atomics).
__global__ void __launch_bounds__(256)
prep_kernel(const float* __restrict__ feat, const long long* __restrict__ labels) {
    __shared__ float wmin[8];
    const int tIdx = threadIdx.x;
    const int lane = tIdx & 31, warp = tIdx >> 5;
    const int g   = blockIdx.x * 256 + tIdx;
    const int row = g >> 4;
    const int sub = g & 15;               // 8 floats per thread
    const float4* src = reinterpret_cast<const float4*>(feat + (size_t)row * KDIM + sub * 8);
    float4 v0 = src[0], v1 = src[1];

    float ss = v0.x*v0.x + v0.y*v0.y + v0.z*v0.z + v0.w*v0.w
             + v1.x*v1.x + v1.y*v1.y + v1.z*v1.z + v1.w*v1.w;

    uint32_t w0 = (uint32_t)pk_e4m3x2(v0.x, v0.y) | ((uint32_t)pk_e4m3x2(v0.z, v0.w) << 16);
    uint32_t w1 = (uint32_t)pk_e4m3x2(v1.x, v1.y) | ((uint32_t)pk_e4m3x2(v1.z, v1.w) << 16);
    *reinterpret_cast<uint2*>(f8G + (size_t)row * KDIM + sub * 8) = make_uint2(w0, w1);

    #pragma unroll
    for (int o = 8; o; o >>= 1) ss += __shfl_xor_sync(0xffffffffu, ss, o);
    const float d = ss * INVT;            // valid on all lanes (16-lane group sum)
    if (sub == 0) {
        dG[row]   = d;
        accG[row] = 0.0f;
        mG[row]   = fenc(d);      // safe finite init: exact when accG stays 0
        labG[row] = (int)labels[row];
    }
    // block-level min of d -> one atomic per CTA
    float dm = d;
    #pragma unroll
    for (int o = 16; o; o >>= 1) dm = fminf(dm, __shfl_xor_sync(0xffffffffu, dm, o));
    if (lane == 0) wmin[warp] = dm;
    __syncthreads();
    if (tIdx == 0) {
        float v = wmin[0];
        #pragma unroll
        for (int i = 1; i < 8; i++) v = fminf(v, wmin[i]);
        atomicMin(&dminEnc, fenc(v));
    }
}

// ---- kernel 2: symmetric FP8 MMA GEMM, hotness-gated epilogue ------------
// (byte-identical to R16 — verified best at 45.8us)
// Tiles tj >= ti only. 128x128 tile (16KB/tile fp8), 8 warps (4x2), 32x64.

#define SMEM_A   0
#define SMEM_B   16384
#define SMEM_SZ  32768

__global__ void __launch_bounds__(256, 2)
main_kernel() {
    const int ti = blockIdx.y, tj = blockIdx.x;
    if (tj < ti) return;
    const bool diag = (ti == tj);

    extern __shared__ char smem[];
    const uint32_t sb = smem_to_u32(smem);
    const int t = threadIdx.x;
    const int lane = t & 31, wid = t >> 5;
    const int wm = wid & 3, wn = wid >> 2;
    const int rowbase = ti * 128;
    const int colbase = tj * 128;

    // ---- load A (rows) and B (cols) tiles, swizzled for ldmatrix ----
    {
        const int q = t & 7, r0 = t >> 3;            // 32 base rows
        const uint32_t sw = (uint32_t)((q ^ (r0 & 7)) * 16);
        const uint8_t* Ag = f8G + (size_t)(rowbase + r0) * KDIM + q * 16;
        const uint8_t* Bg = f8G + (size_t)(colbase + r0) * KDIM + q * 16;
        #pragma unroll
        for (int j = 0; j < 4; j++) {
            cpa16(sb + SMEM_A + (r0 + j * 32) * 128 + sw, Ag + (size_t)j * 32 * KDIM);
            cpa16(sb + SMEM_B + (r0 + j * 32) * 128 + sw, Bg + (size_t)j * 32 * KDIM);
        }
    }
    asm volatile("cp.async.commit_group;" ::: "memory");
    asm volatile("cp.async.wait_group 0;" ::: "memory");
    __syncthreads();

    // ---- GEMM: K=128 in 4 steps of k32 ----
    float acc[2][8][4];
    #pragma unroll
    for (int mi = 0; mi < 2; mi++)
        #pragma unroll
        for (int bi = 0; bi < 8; bi++)
            #pragma unroll
            for (int rg = 0; rg < 4; rg++) acc[mi][bi][rg] = 0.f;

    #pragma unroll
    for (int ks = 0; ks < 4; ks++) {
        const int ql = ks * 2 + (lane >> 4);         // quad 0..7
        uint32_t af[2][4];
        #pragma unroll
        for (int mi = 0; mi < 2; mi++) {
            int row = wm * 32 + mi * 16 + (lane & 15);
            ldsm4(af[mi], sb + SMEM_A + row * 128 + ((ql ^ (row & 7)) * 16));
        }
        uint32_t bfm[4][4];
        #pragma unroll
        for (int bi = 0; bi < 4; bi++) {
            int row = wn * 64 + bi * 16 + (lane & 15);
            ldsm4(bfm[bi], sb + SMEM_B + row * 128 + ((ql ^ (row & 7)) * 16));
        }
        #pragma unroll
        for (int mi = 0; mi < 2; mi++)
            #pragma unroll
            for (int bi = 0; bi < 4; bi++) {
                mma16832f8(acc[mi][bi * 2 + 0], af[mi], bfm[bi][0], bfm[bi][2]);
                mma16832f8(acc[mi][bi * 2 + 1], af[mi], bfm[bi][1], bfm[bi][3]);
            }
    }

    // ---- hotness detection: per-slot maxes (element-floor cost) ----
    const float thrC = fdec(dminEnc) * 0.2f - 15.f;   // raw-sim conservative threshold
    float m4[4];
    #pragma unroll
    for (int s = 0; s < 4; s++) {
        float m = -1e30f;
        #pragma unroll
        for (int bi = 0; bi < 8; bi++) {
            m = fmaxf(m, acc[s >> 1][bi][(s & 1) * 2]);
            m = fmaxf(m, acc[s >> 1][bi][(s & 1) * 2 + 1]);
        }
        m4[s] = m;
    }
    const float tmax = fmaxf(fmaxf(m4[0], m4[1]), fmaxf(m4[2], m4[3]));
    const bool hot = __any_sync(0xffffffffu, tmax > thrC);

    if (__builtin_expect(hot, 0)) {
        // ---- full exact epilogue (rare: diagonal tiles + any true outlier) ----
        // row side
        #pragma unroll
        for (int s = 0; s < 4; s++) {
            const int gr = rowbase + wm * 32 + (s >> 1) * 16 + (s & 1) * 8 + (lane >> 2);
            float m = m4[s];
            m = fmaxf(m, __shfl_xor_sync(0xffffffffu, m, 1));
            m = fmaxf(m, __shfl_xor_sync(0xffffffffu, m, 2));
            const float d = dG[gr];
            if (m * INVT - d > -75.f) {
                const int lr = labG[gr];
                #pragma unroll
                for (int bi = 0; bi < 8; bi++)
                    #pragma unroll
                    for (int rgl = 0; rgl < 2; rgl++) {
                        float sim = acc[s >> 1][bi][(s & 1) * 2 + rgl] * INVT;
                        float tt  = sim - d;
                        if (tt > -75.f) {
                            int c = colbase + wn * 64 + bi * 8 + (lane & 3) * 2 + rgl;
                            if (c != gr) {
                                float e = __expf(tt);
                                atomicAdd(&accG[gr], (lr == labG[c]) ? e : -e);
                            }
                        }
                    }
            }
            if ((lane & 3) == 0) atomicMax(&mG[gr], fenc(m * INVT));
        }
        // col side (transposed contribution), off-diagonal tiles only
        if (!diag) {
            #pragma unroll
            for (int bi = 0; bi < 8; bi++)
                #pragma unroll
                for (int rgl = 0; rgl < 2; rgl++) {
                    float m = fmaxf(fmaxf(acc[0][bi][rgl], acc[0][bi][2 + rgl]),
                                    fmaxf(acc[1][bi][rgl], acc[1][bi][2 + rgl]));
                    m = fmaxf(m, __shfl_xor_sync(0xffffffffu, m, 4));
                    m = fmaxf(m, __shfl_xor_sync(0xffffffffu, m, 8));
                    m = fmaxf(m, __shfl_xor_sync(0xffffffffu, m, 16));
                    if (m > thrC) {
                        const int c  = colbase + wn * 64 + bi * 8 + (lane & 3) * 2 + rgl;
                        const float dc = dG[c];
                        const int lc = labG[c];
                        #pragma unroll
                        for (int mi = 0; mi < 2; mi++)
                            #pragma unroll
                            for (int rgh = 0; rgh < 2; rgh++) {
                                float sim = acc[mi][bi][rgh * 2 + rgl] * INVT;
                                float tt  = sim - dc;
                                if (tt > -75.f) {
                                    int r = rowbase + wm * 32 + mi * 16 + rgh * 8 + (lane >> 2);
                                    float e = __expf(tt);
                                    atomicAdd(&accG[c], (labG[r] == lc) ? e : -e);
                                }
                            }
                    }
                    if (lane < 4) {
                        int c = colbase + wn * 64 + bi * 8 + lane * 2 + rgl;
                        atomicMax(&mG[c], fenc(m * INVT));
                    }
                }
        }
    }
    // non-hot warps: contribute nothing (proof: any element passing a per-element
    // exp guard implies raw > thrC -> warp hot; if accG[r] != 0, the warp owning
    // the true row max is hot and writes it; if accG[r] == 0, mG init dG suffices).
}

// ---- kernel 3: exact max rebase + mean -----------------------------------
__global__ void final_kernel(float* __restrict__ out) {
    __shared__ double red[32];
    const int t = threadIdx.x, lane = t & 31, warp = t >> 5;
    double s = 0.0;
    #pragma unroll
    for (int i = 0; i < 8; i++) {
        int r = t + i * 1024;
        float m = fdec(mG[r]);
        s += (double)(accG[r] * __expf(dG[r] - m));
    }
    #pragma unroll
    for (int o = 16; o; o >>= 1) s += __shfl_xor_sync(0xffffffffu, s, o);
    if (lane == 0) red[warp] = s;
    __syncthreads();
    if (warp == 0) {
        double v = red[lane];
        #pragma unroll
        for (int o = 16; o; o >>= 1) v += __shfl_xor_sync(0xffffffffu, v, o);
        if (lane == 0) out[0] = (float)(-v / (double)M_TOTAL);
    }
}

// ---- host ----------------------------------------------------------------
extern "C" void kernel_launch(void* const* d_in, const int* in_sizes, int n_in,
                              void* d_out, int out_size) {
    const float*     feat   = (const float*)d_in[0];
    const long long* labels = (const long long*)d_in[1];
    float* out = (float*)d_out;

    cudaFuncSetAttribute(main_kernel, cudaFuncAttributeMaxDynamicSharedMemorySize, SMEM_SZ);

    prep_kernel<<<M_TOTAL * 16 / 256, 256>>>(feat, labels);
    main_kernel<<<dim3(64, 64), 256, SMEM_SZ>>>();
    final_kernel<<<1, 1024>>>(out);
}